// round 2
// baseline (speedup 1.0000x reference)
#include <cuda_runtime.h>
#include <math.h>

#define N_NODES 100000
#define D 128
#define LN_EPS 1e-5f

// Scratch (allocation-free rule: __device__ globals)
__device__ float g_agg[N_NODES * D];
__device__ int   g_cnt[N_NODES];

typedef unsigned long long ull;

__device__ __forceinline__ ull pack2(float lo, float hi) {
    ull r;
    asm("mov.b64 %0, {%1, %2};" : "=l"(r) : "f"(lo), "f"(hi));
    return r;
}
__device__ __forceinline__ void unpack2(ull v, float& lo, float& hi) {
    asm("mov.b64 {%0, %1}, %2;" : "=f"(lo), "=f"(hi) : "l"(v));
}
__device__ __forceinline__ ull fma2(ull a, ull b, ull c) {
    ull d;
    asm("fma.rn.f32x2 %0, %1, %2, %3;" : "=l"(d) : "l"(a), "l"(b), "l"(c));
    return d;
}

__device__ __forceinline__ float gelu_exact(float t) {
    return 0.5f * t * (1.0f + erff(t * 0.70710678118654752440f));
}

// ---------------------------------------------------------------------------
// Kernel 1: zero agg + cnt
// ---------------------------------------------------------------------------
__global__ void zero_kernel() {
    int i = blockIdx.x * blockDim.x + threadIdx.x;
    const int n4 = N_NODES * D / 4;
    if (i < n4) {
        reinterpret_cast<float4*>(g_agg)[i] = make_float4(0.f, 0.f, 0.f, 0.f);
    }
    if (i < N_NODES) g_cnt[i] = 0;
}

// ---------------------------------------------------------------------------
// Kernel 2: edge scatter. One warp per edge: gather x[src] (512B coalesced),
// vector float4 reduction into agg[dst]. Lane 0 bumps the count.
// edge_index is int32 on device (JAX x64 disabled downcasts int64 -> int32).
// ---------------------------------------------------------------------------
__global__ void scatter_kernel(const float* __restrict__ x,
                               const int* __restrict__ ei, int E) {
    int gwarp = (blockIdx.x * blockDim.x + threadIdx.x) >> 5;
    int lane  = threadIdx.x & 31;
    if (gwarp >= E) return;
    int src = ei[gwarp];
    int dst = ei[E + gwarp];
    if ((unsigned)src >= N_NODES || (unsigned)dst >= N_NODES) return; // safety
    float4 v = reinterpret_cast<const float4*>(x + (size_t)src * D)[lane];
    float* a = g_agg + (size_t)dst * D + lane * 4;
    asm volatile("red.global.add.v4.f32 [%0], {%1,%2,%3,%4};"
                 :: "l"(a), "f"(v.x), "f"(v.y), "f"(v.z), "f"(v.w) : "memory");
    if (lane == 0) atomicAdd(&g_cnt[dst], 1);
}

// ---------------------------------------------------------------------------
// Kernel 3: fused GEMM + bias + GELU + LayerNorm + residual.
// out = LN(gelu([agg/cnt | x] @ [W_l | W_r]^T + b_l)) + x
// Block: 512 threads, tile = 128 rows. Warp handles 8 rows (4 f32x2 pairs),
// each lane covers 4 output columns.
// ---------------------------------------------------------------------------
#define W_STRIDE 132           // 16B-aligned float4 loads, spreads banks on store
#define A_STRIDE 33
#define SMEM_FLOATS (256 * W_STRIDE + 128 * A_STRIDE + 128)
#define SMEM_BYTES (SMEM_FLOATS * 4)

__global__ void __launch_bounds__(512, 1)
gemm_fused_kernel(const float* __restrict__ x,
                  const float* __restrict__ W_l,
                  const float* __restrict__ b_l,
                  const float* __restrict__ W_r,
                  const float* __restrict__ ln_gamma,
                  const float* __restrict__ ln_beta,
                  float* __restrict__ out) {
    extern __shared__ float smem[];
    float* Wc   = smem;                       // [256][W_STRIDE]: Wc[k][n]
    float* As   = smem + 256 * W_STRIDE;      // [128][A_STRIDE]
    float* rinv = As + 128 * A_STRIDE;        // [128]

    const int tid  = threadIdx.x;
    const int lane = tid & 31;
    const int warp = tid >> 5;
    const int row0 = blockIdx.x * 128;

    // Stage combined weight, transposed: Wc[k + 128*m][n] = W_m[n][k]
    for (int idx = tid; idx < 2 * D * D; idx += 512) {
        int m = idx >> 14;            // 0 = W_l, 1 = W_r
        int n = (idx >> 7) & 127;
        int k = idx & 127;
        float w = m ? W_r[n * D + k] : W_l[n * D + k];
        Wc[(m * 128 + k) * W_STRIDE + n] = w;
    }
    if (tid < 128) {
        int row = row0 + tid;
        rinv[tid] = (row < N_NODES) ? 1.0f / fmaxf((float)g_cnt[row], 1.0f) : 0.0f;
    }
    __syncthreads();

    ull acc[4][4];
    #pragma unroll
    for (int j = 0; j < 4; j++)
        #pragma unroll
        for (int c = 0; c < 4; c++) acc[j][c] = 0ull;

    const int wr0 = warp * 8;

    for (int kc = 0; kc < 256; kc += 32) {
        // Stage A chunk: As[r][k] = (k<128 ? agg*rinv : x)
        for (int idx = tid; idx < 128 * 32; idx += 512) {
            int r = idx >> 5;
            int k = idx & 31;
            int row = row0 + r;
            int kk = kc + k;
            float v = 0.0f;
            if (row < N_NODES) {
                if (kk < 128) v = g_agg[(size_t)row * D + kk] * rinv[r];
                else          v = x[(size_t)row * D + (kk - 128)];
            }
            As[r * A_STRIDE + k] = v;
        }
        __syncthreads();

        #pragma unroll
        for (int k = 0; k < 32; k++) {
            const float4 wv = *reinterpret_cast<const float4*>(
                &Wc[(kc + k) * W_STRIDE + lane * 4]);
            ull w0 = pack2(wv.x, wv.x);
            ull w1 = pack2(wv.y, wv.y);
            ull w2 = pack2(wv.z, wv.z);
            ull w3 = pack2(wv.w, wv.w);
            #pragma unroll
            for (int j = 0; j < 4; j++) {
                float a0 = As[(wr0 + 2 * j) * A_STRIDE + k];
                float a1 = As[(wr0 + 2 * j + 1) * A_STRIDE + k];
                ull a2 = pack2(a0, a1);
                acc[j][0] = fma2(a2, w0, acc[j][0]);
                acc[j][1] = fma2(a2, w1, acc[j][1]);
                acc[j][2] = fma2(a2, w2, acc[j][2]);
                acc[j][3] = fma2(a2, w3, acc[j][3]);
            }
        }
        __syncthreads();
    }

    // Epilogue: bias + GELU + LayerNorm + residual, one row per warp-pass
    const float4 blv = *reinterpret_cast<const float4*>(&b_l[lane * 4]);
    const float4 gmv = *reinterpret_cast<const float4*>(&ln_gamma[lane * 4]);
    const float4 btv = *reinterpret_cast<const float4*>(&ln_beta[lane * 4]);

    #pragma unroll
    for (int j = 0; j < 4; j++) {
        float v0[4], v1[4];
        #pragma unroll
        for (int c = 0; c < 4; c++) unpack2(acc[j][c], v0[c], v1[c]);

        #pragma unroll
        for (int h = 0; h < 2; h++) {
            float g0, g1, g2, g3;
            if (h == 0) {
                g0 = gelu_exact(v0[0] + blv.x);
                g1 = gelu_exact(v0[1] + blv.y);
                g2 = gelu_exact(v0[2] + blv.z);
                g3 = gelu_exact(v0[3] + blv.w);
            } else {
                g0 = gelu_exact(v1[0] + blv.x);
                g1 = gelu_exact(v1[1] + blv.y);
                g2 = gelu_exact(v1[2] + blv.z);
                g3 = gelu_exact(v1[3] + blv.w);
            }
            float s  = g0 + g1 + g2 + g3;
            float ss = fmaf(g0, g0, fmaf(g1, g1, fmaf(g2, g2, g3 * g3)));
            #pragma unroll
            for (int off = 16; off > 0; off >>= 1) {
                s  += __shfl_xor_sync(0xffffffffu, s,  off);
                ss += __shfl_xor_sync(0xffffffffu, ss, off);
            }
            float mu   = s * (1.0f / 128.0f);
            float var  = ss * (1.0f / 128.0f) - mu * mu;
            float rstd = rsqrtf(var + LN_EPS);

            int row = row0 + wr0 + 2 * j + h;
            if (row < N_NODES) {
                float4 xr = *reinterpret_cast<const float4*>(
                    &x[(size_t)row * D + lane * 4]);
                float4 o;
                o.x = (g0 - mu) * rstd * gmv.x + btv.x + xr.x;
                o.y = (g1 - mu) * rstd * gmv.y + btv.y + xr.y;
                o.z = (g2 - mu) * rstd * gmv.z + btv.z + xr.z;
                o.w = (g3 - mu) * rstd * gmv.w + btv.w + xr.w;
                *reinterpret_cast<float4*>(&out[(size_t)row * D + lane * 4]) = o;
            }
        }
    }
}

// ---------------------------------------------------------------------------
extern "C" void kernel_launch(void* const* d_in, const int* in_sizes, int n_in,
                              void* d_out, int out_size) {
    const float* x     = (const float*)d_in[0];
    const int*   ei    = (const int*)d_in[1];
    const float* W_l   = (const float*)d_in[2];
    const float* b_l   = (const float*)d_in[3];
    const float* W_r   = (const float*)d_in[4];
    const float* gamma = (const float*)d_in[5];
    const float* beta  = (const float*)d_in[6];
    float*       out   = (float*)d_out;

    const int E = in_sizes[1] / 2;

    cudaFuncSetAttribute(gemm_fused_kernel,
                         cudaFuncAttributeMaxDynamicSharedMemorySize, SMEM_BYTES);

    const int n4 = N_NODES * D / 4;
    zero_kernel<<<(n4 + 255) / 256, 256>>>();

    long long total_threads = (long long)E * 32;
    int sblocks = (int)((total_threads + 255) / 256);
    scatter_kernel<<<sblocks, 256>>>(x, ei, E);

    int gblocks = (N_NODES + 127) / 128;
    gemm_fused_kernel<<<gblocks, 512, SMEM_BYTES>>>(x, W_l, b_l, W_r,
                                                    gamma, beta, out);
}

// round 3
// speedup vs baseline: 1.1736x; 1.1736x over previous
#include <cuda_runtime.h>
#include <math.h>

#define N_NODES 100000
#define D 128
#define E_MAX 1600000
#define LN_EPS 1e-5f

// Scratch (allocation-free rule: __device__ globals)
__device__ float g_agg[N_NODES * D];     // normalized mean aggregation
__device__ int   g_cnt[N_NODES];
__device__ int   g_off[N_NODES + 1];
__device__ int   g_pos[N_NODES];
__device__ int   g_csr[E_MAX];
__device__ int   g_bsum[128];

typedef unsigned long long ull;

__device__ __forceinline__ ull pack2(float lo, float hi) {
    ull r;
    asm("mov.b64 %0, {%1, %2};" : "=l"(r) : "f"(lo), "f"(hi));
    return r;
}
__device__ __forceinline__ void unpack2(ull v, float& lo, float& hi) {
    asm("mov.b64 {%0, %1}, %2;" : "=f"(lo), "=f"(hi) : "l"(v));
}
__device__ __forceinline__ ull fma2(ull a, ull b, ull c) {
    ull d;
    asm("fma.rn.f32x2 %0, %1, %2, %3;" : "=l"(d) : "l"(a), "l"(b), "l"(c));
    return d;
}

__device__ __forceinline__ float gelu_exact(float t) {
    return 0.5f * t * (1.0f + erff(t * 0.70710678118654752440f));
}

// ---------------------------------------------------------------------------
// Phase 1: CSR build (histogram -> 2-level exclusive scan -> index scatter)
// ---------------------------------------------------------------------------
__global__ void zero_cnt_kernel() {
    int i = blockIdx.x * blockDim.x + threadIdx.x;
    if (i < N_NODES) g_cnt[i] = 0;
}

__global__ void hist_kernel(const int* __restrict__ ei, int E) {
    int i = blockIdx.x * blockDim.x + threadIdx.x;
    if (i >= E) return;
    int dst = ei[E + i];
    if ((unsigned)dst < N_NODES) atomicAdd(&g_cnt[dst], 1);
}

#define SCAN_B 1024
__global__ void scan_partial_kernel(int n) {
    __shared__ int sdata[SCAN_B];
    int tid = threadIdx.x;
    int i = blockIdx.x * SCAN_B + tid;
    int v = (i < n) ? g_cnt[i] : 0;
    sdata[tid] = v;
    __syncthreads();
    for (int off = 1; off < SCAN_B; off <<= 1) {
        int t = (tid >= off) ? sdata[tid - off] : 0;
        __syncthreads();
        sdata[tid] += t;
        __syncthreads();
    }
    if (i < n) g_off[i] = sdata[tid] - v;   // exclusive within block
    if (tid == SCAN_B - 1) g_bsum[blockIdx.x] = sdata[tid];
}

__global__ void scan_sums_kernel(int nb) {
    __shared__ int sdata[128];
    int tid = threadIdx.x;
    int v = (tid < nb) ? g_bsum[tid] : 0;
    sdata[tid] = v;
    __syncthreads();
    for (int off = 1; off < 128; off <<= 1) {
        int t = (tid >= off) ? sdata[tid - off] : 0;
        __syncthreads();
        sdata[tid] += t;
        __syncthreads();
    }
    if (tid < nb) g_bsum[tid] = sdata[tid] - v;   // exclusive
}

__global__ void scan_add_kernel(int n, int E) {
    int i = blockIdx.x * blockDim.x + threadIdx.x;
    if (i < n) {
        int o = g_off[i] + g_bsum[blockIdx.x * blockDim.x / SCAN_B +
                                  (threadIdx.x + blockIdx.x * blockDim.x) / SCAN_B -
                                  (blockIdx.x * blockDim.x) / SCAN_B];
        // (simplify: recompute block id of element i in the SCAN_B partition)
        o = g_off[i] + g_bsum[i / SCAN_B];
        g_off[i] = o;
        g_pos[i] = o;
    }
    if (i == 0) g_off[n] = E;
}

__global__ void csr_fill_kernel(const int* __restrict__ ei, int E) {
    int i = blockIdx.x * blockDim.x + threadIdx.x;
    if (i >= E) return;
    int dst = ei[E + i];
    int src = ei[i];
    if ((unsigned)dst >= N_NODES || (unsigned)src >= N_NODES) return;
    int p = atomicAdd(&g_pos[dst], 1);
    g_csr[p] = src;
}

// ---------------------------------------------------------------------------
// Phase 2: gather-aggregate. One warp per destination node; lane covers 4
// feature columns (float4). Register accumulation, no atomics. Writes the
// normalized mean directly.
// ---------------------------------------------------------------------------
__global__ void __launch_bounds__(256)
aggregate_kernel(const float* __restrict__ x) {
    int gwarp = (blockIdx.x * blockDim.x + threadIdx.x) >> 5;
    int lane  = threadIdx.x & 31;
    if (gwarp >= N_NODES) return;
    int beg = g_off[gwarp];
    int end = g_off[gwarp + 1];
    float4 acc = make_float4(0.f, 0.f, 0.f, 0.f);
    const float4* x4 = reinterpret_cast<const float4*>(x);

    int e = beg;
    int src_next = (e < end) ? g_csr[e] : 0;
    while (e < end) {
        int src = src_next;
        ++e;
        src_next = (e < end) ? g_csr[e] : 0;
        float4 v = x4[(size_t)src * 32 + lane];
        acc.x += v.x; acc.y += v.y; acc.z += v.z; acc.w += v.w;
    }
    float rinv = 1.0f / fmaxf((float)(end - beg), 1.0f);
    acc.x *= rinv; acc.y *= rinv; acc.z *= rinv; acc.w *= rinv;
    reinterpret_cast<float4*>(g_agg)[(size_t)gwarp * 32 + lane] = acc;
}

// ---------------------------------------------------------------------------
// Phase 3: fused GEMM + bias + GELU + LayerNorm + residual.
// out = LN(gelu([agg | x] @ [W_l | W_r]^T + b_l)) + x
// ---------------------------------------------------------------------------
#define W_STRIDE 132
#define A_STRIDE 33
#define SMEM_FLOATS (256 * W_STRIDE + 128 * A_STRIDE)
#define SMEM_BYTES (SMEM_FLOATS * 4)

__global__ void __launch_bounds__(512, 1)
gemm_fused_kernel(const float* __restrict__ x,
                  const float* __restrict__ W_l,
                  const float* __restrict__ b_l,
                  const float* __restrict__ W_r,
                  const float* __restrict__ ln_gamma,
                  const float* __restrict__ ln_beta,
                  float* __restrict__ out) {
    extern __shared__ float smem[];
    float* Wc = smem;                       // [256][W_STRIDE]: Wc[k][n]
    float* As = smem + 256 * W_STRIDE;      // [128][A_STRIDE]

    const int tid  = threadIdx.x;
    const int lane = tid & 31;
    const int warp = tid >> 5;
    const int row0 = blockIdx.x * 128;

    // Stage combined weight, transposed: Wc[k + 128*m][n] = W_m[n][k]
    for (int idx = tid; idx < 2 * D * D; idx += 512) {
        int m = idx >> 14;            // 0 = W_l, 1 = W_r
        int n = (idx >> 7) & 127;
        int k = idx & 127;
        float w = m ? W_r[n * D + k] : W_l[n * D + k];
        Wc[(m * 128 + k) * W_STRIDE + n] = w;
    }
    __syncthreads();

    ull acc[4][4];
    #pragma unroll
    for (int j = 0; j < 4; j++)
        #pragma unroll
        for (int c = 0; c < 4; c++) acc[j][c] = 0ull;

    const int wr0 = warp * 8;

    for (int kc = 0; kc < 256; kc += 32) {
        for (int idx = tid; idx < 128 * 32; idx += 512) {
            int r = idx >> 5;
            int k = idx & 31;
            int row = row0 + r;
            int kk = kc + k;
            float v = 0.0f;
            if (row < N_NODES) {
                if (kk < 128) v = g_agg[(size_t)row * D + kk];
                else          v = x[(size_t)row * D + (kk - 128)];
            }
            As[r * A_STRIDE + k] = v;
        }
        __syncthreads();

        #pragma unroll
        for (int k = 0; k < 32; k++) {
            const float4 wv = *reinterpret_cast<const float4*>(
                &Wc[(kc + k) * W_STRIDE + lane * 4]);
            ull w0 = pack2(wv.x, wv.x);
            ull w1 = pack2(wv.y, wv.y);
            ull w2 = pack2(wv.z, wv.z);
            ull w3 = pack2(wv.w, wv.w);
            #pragma unroll
            for (int j = 0; j < 4; j++) {
                float a0 = As[(wr0 + 2 * j) * A_STRIDE + k];
                float a1 = As[(wr0 + 2 * j + 1) * A_STRIDE + k];
                ull a2 = pack2(a0, a1);
                acc[j][0] = fma2(a2, w0, acc[j][0]);
                acc[j][1] = fma2(a2, w1, acc[j][1]);
                acc[j][2] = fma2(a2, w2, acc[j][2]);
                acc[j][3] = fma2(a2, w3, acc[j][3]);
            }
        }
        __syncthreads();
    }

    // Epilogue: bias + GELU + LayerNorm + residual
    const float4 blv = *reinterpret_cast<const float4*>(&b_l[lane * 4]);
    const float4 gmv = *reinterpret_cast<const float4*>(&ln_gamma[lane * 4]);
    const float4 btv = *reinterpret_cast<const float4*>(&ln_beta[lane * 4]);

    #pragma unroll
    for (int j = 0; j < 4; j++) {
        float v0[4], v1[4];
        #pragma unroll
        for (int c = 0; c < 4; c++) unpack2(acc[j][c], v0[c], v1[c]);

        #pragma unroll
        for (int h = 0; h < 2; h++) {
            float g0, g1, g2, g3;
            if (h == 0) {
                g0 = gelu_exact(v0[0] + blv.x);
                g1 = gelu_exact(v0[1] + blv.y);
                g2 = gelu_exact(v0[2] + blv.z);
                g3 = gelu_exact(v0[3] + blv.w);
            } else {
                g0 = gelu_exact(v1[0] + blv.x);
                g1 = gelu_exact(v1[1] + blv.y);
                g2 = gelu_exact(v1[2] + blv.z);
                g3 = gelu_exact(v1[3] + blv.w);
            }
            float s  = g0 + g1 + g2 + g3;
            float ss = fmaf(g0, g0, fmaf(g1, g1, fmaf(g2, g2, g3 * g3)));
            #pragma unroll
            for (int off = 16; off > 0; off >>= 1) {
                s  += __shfl_xor_sync(0xffffffffu, s,  off);
                ss += __shfl_xor_sync(0xffffffffu, ss, off);
            }
            float mu   = s * (1.0f / 128.0f);
            float var  = ss * (1.0f / 128.0f) - mu * mu;
            float rstd = rsqrtf(var + LN_EPS);

            int row = row0 + wr0 + 2 * j + h;
            if (row < N_NODES) {
                float4 xr = *reinterpret_cast<const float4*>(
                    &x[(size_t)row * D + lane * 4]);
                float4 o;
                o.x = (g0 - mu) * rstd * gmv.x + btv.x + xr.x;
                o.y = (g1 - mu) * rstd * gmv.y + btv.y + xr.y;
                o.z = (g2 - mu) * rstd * gmv.z + btv.z + xr.z;
                o.w = (g3 - mu) * rstd * gmv.w + btv.w + xr.w;
                *reinterpret_cast<float4*>(&out[(size_t)row * D + lane * 4]) = o;
            }
        }
    }
}

// ---------------------------------------------------------------------------
extern "C" void kernel_launch(void* const* d_in, const int* in_sizes, int n_in,
                              void* d_out, int out_size) {
    const float* x     = (const float*)d_in[0];
    const int*   ei    = (const int*)d_in[1];
    const float* W_l   = (const float*)d_in[2];
    const float* b_l   = (const float*)d_in[3];
    const float* W_r   = (const float*)d_in[4];
    const float* gamma = (const float*)d_in[5];
    const float* beta  = (const float*)d_in[6];
    float*       out   = (float*)d_out;

    int E = in_sizes[1] / 2;
    if (E > E_MAX) E = E_MAX;

    cudaFuncSetAttribute(gemm_fused_kernel,
                         cudaFuncAttributeMaxDynamicSharedMemorySize, SMEM_BYTES);

    // CSR build
    zero_cnt_kernel<<<(N_NODES + 255) / 256, 256>>>();
    hist_kernel<<<(E + 255) / 256, 256>>>(ei, E);
    int nb = (N_NODES + SCAN_B - 1) / SCAN_B;          // 98 blocks
    scan_partial_kernel<<<nb, SCAN_B>>>(N_NODES);
    scan_sums_kernel<<<1, 128>>>(nb);
    scan_add_kernel<<<(N_NODES + 255) / 256, 256>>>(N_NODES, E);
    csr_fill_kernel<<<(E + 255) / 256, 256>>>(ei, E);

    // Gather-aggregate (no atomics on features)
    long long athreads = (long long)N_NODES * 32;
    aggregate_kernel<<<(int)((athreads + 255) / 256), 256>>>(x);

    // Fused GEMM + epilogue
    int gblocks = (N_NODES + 127) / 128;
    gemm_fused_kernel<<<gblocks, 512, SMEM_BYTES>>>(x, W_l, b_l, W_r,
                                                    gamma, beta, out);
}

// round 5
// speedup vs baseline: 1.3007x; 1.1083x over previous
#include <cuda_runtime.h>
#include <math.h>
#include <stdint.h>

#define N_NODES 100000
#define D 128
#define E_MAX 1600000
#define LN_EPS 1e-5f

// Scratch (allocation-free rule: __device__ globals)
__device__ float g_agg[N_NODES * D];     // normalized mean aggregation
__device__ int   g_cnt[N_NODES];
__device__ int   g_off[N_NODES + 1];
__device__ int   g_pos[N_NODES];
__device__ int   g_csr[E_MAX];
__device__ int   g_bsum[128];

__device__ __forceinline__ float gelu_exact(float t) {
    return 0.5f * t * (1.0f + erff(t * 0.70710678118654752440f));
}

__device__ __forceinline__ uint32_t smem_u32(const void* p) {
    uint32_t a;
    asm("{ .reg .u64 t; cvta.to.shared.u64 t, %1; cvt.u32.u64 %0, t; }"
        : "=r"(a) : "l"(p));
    return a;
}
__device__ __forceinline__ uint32_t f2tf32(float f) {
    uint32_t r; asm("cvt.rna.tf32.f32 %0, %1;" : "=r"(r) : "f"(f)); return r;
}

// ---------------------------------------------------------------------------
// Phase 1: CSR build (histogram -> 2-level exclusive scan -> index scatter)
// ---------------------------------------------------------------------------
__global__ void zero_cnt_kernel() {
    int i = blockIdx.x * blockDim.x + threadIdx.x;
    if (i < N_NODES) g_cnt[i] = 0;
}

__global__ void hist_kernel(const int* __restrict__ ei, int E) {
    int i = blockIdx.x * blockDim.x + threadIdx.x;
    if (i >= E) return;
    int dst = ei[E + i];
    if ((unsigned)dst < N_NODES) atomicAdd(&g_cnt[dst], 1);
}

#define SCAN_B 1024
__global__ void scan_partial_kernel(int n) {
    __shared__ int sdata[SCAN_B];
    int tid = threadIdx.x;
    int i = blockIdx.x * SCAN_B + tid;
    int v = (i < n) ? g_cnt[i] : 0;
    sdata[tid] = v;
    __syncthreads();
    for (int off = 1; off < SCAN_B; off <<= 1) {
        int t = (tid >= off) ? sdata[tid - off] : 0;
        __syncthreads();
        sdata[tid] += t;
        __syncthreads();
    }
    if (i < n) g_off[i] = sdata[tid] - v;   // exclusive within block
    if (tid == SCAN_B - 1) g_bsum[blockIdx.x] = sdata[tid];
}

__global__ void scan_sums_kernel(int nb) {
    __shared__ int sdata[128];
    int tid = threadIdx.x;
    int v = (tid < nb) ? g_bsum[tid] : 0;
    sdata[tid] = v;
    __syncthreads();
    for (int off = 1; off < 128; off <<= 1) {
        int t = (tid >= off) ? sdata[tid - off] : 0;
        __syncthreads();
        sdata[tid] += t;
        __syncthreads();
    }
    if (tid < nb) g_bsum[tid] = sdata[tid] - v;   // exclusive
}

__global__ void scan_add_kernel(int n, int E) {
    int i = blockIdx.x * blockDim.x + threadIdx.x;
    if (i < n) {
        int o = g_off[i] + g_bsum[i / SCAN_B];
        g_off[i] = o;
        g_pos[i] = o;
    }
    if (i == 0) g_off[n] = E;
}

__global__ void csr_fill_kernel(const int* __restrict__ ei, int E) {
    int i = blockIdx.x * blockDim.x + threadIdx.x;
    if (i >= E) return;
    int dst = ei[E + i];
    int src = ei[i];
    if ((unsigned)dst >= N_NODES || (unsigned)src >= N_NODES) return;
    int p = atomicAdd(&g_pos[dst], 1);
    g_csr[p] = src;
}

// ---------------------------------------------------------------------------
// Phase 2: gather-aggregate. One warp per destination node. No atomics.
// ---------------------------------------------------------------------------
__global__ void __launch_bounds__(256)
aggregate_kernel(const float* __restrict__ x) {
    int gwarp = (blockIdx.x * blockDim.x + threadIdx.x) >> 5;
    int lane  = threadIdx.x & 31;
    if (gwarp >= N_NODES) return;
    int beg = g_off[gwarp];
    int end = g_off[gwarp + 1];
    float4 acc = make_float4(0.f, 0.f, 0.f, 0.f);
    const float4* x4 = reinterpret_cast<const float4*>(x);

    int e = beg;
    for (; e + 1 < end; e += 2) {
        int s0 = g_csr[e], s1 = g_csr[e + 1];
        float4 v0 = x4[(size_t)s0 * 32 + lane];
        float4 v1 = x4[(size_t)s1 * 32 + lane];
        acc.x += v0.x + v1.x; acc.y += v0.y + v1.y;
        acc.z += v0.z + v1.z; acc.w += v0.w + v1.w;
    }
    if (e < end) {
        float4 v = x4[(size_t)g_csr[e] * 32 + lane];
        acc.x += v.x; acc.y += v.y; acc.z += v.z; acc.w += v.w;
    }
    float rinv = 1.0f / fmaxf((float)(end - beg), 1.0f);
    acc.x *= rinv; acc.y *= rinv; acc.z *= rinv; acc.w *= rinv;
    reinterpret_cast<float4*>(g_agg)[(size_t)gwarp * 32 + lane] = acc;
}

// ---------------------------------------------------------------------------
// Phase 3: 3xTF32 mma.sync GEMM + bias + GELU + LayerNorm + residual.
// out = LN(gelu([agg | x] @ [W_l | W_r]^T + b_l)) + x
// CTA: 256 threads (8 warps, 4x2 warp grid), tile M=128 rows x N=128 cols,
// K=256 in 8 chunks of 32. Operands stored in smem as interleaved
// (hi,lo,hi,lo) 16B slots so each mma fragment is a single lds.128.
// ---------------------------------------------------------------------------
#define SM_A  0          // 128 rows * 256 B  = 32768
#define SM_B  32768      // 128 rows * 256 B  = 32768
#define SM_C  0          // reuse: 128 * 132 * 4 = 67584
#define SM_BL 68608
#define SM_GA 69120
#define SM_BE 69632
#define SM_PS 70144      // 256 floats partial sums
#define SM_PSS 71168     // 256 floats partial sumsq
#define SMEM_G 72192

#define MMA3(accp, A0,A1,A2,A3, B0,B1) \
    asm volatile("mma.sync.aligned.m16n8k8.row.col.f32.tf32.tf32.f32 " \
        "{%0,%1,%2,%3}, {%4,%5,%6,%7}, {%8,%9}, {%0,%1,%2,%3};" \
        : "+f"((accp)[0]), "+f"((accp)[1]), "+f"((accp)[2]), "+f"((accp)[3]) \
        : "r"(A0), "r"(A1), "r"(A2), "r"(A3), "r"(B0), "r"(B1))

__device__ __forceinline__ void lds128(uint32_t addr, uint32_t& r0, uint32_t& r1,
                                       uint32_t& r2, uint32_t& r3) {
    asm volatile("ld.shared.v4.b32 {%0,%1,%2,%3}, [%4];"
                 : "=r"(r0), "=r"(r1), "=r"(r2), "=r"(r3) : "r"(addr));
}
__device__ __forceinline__ void sts64(uint32_t addr, uint32_t a, uint32_t b) {
    asm volatile("st.shared.v2.b32 [%0], {%1,%2};"
                 :: "r"(addr), "r"(a), "r"(b) : "memory");
}

// Store one fp32 value as (hi,lo) tf32 pair into the swizzled operand tile.
__device__ __forceinline__ void stage_elem(uint32_t base, int m, int j, float f) {
    int ks = j >> 3, r = j & 7;
    uint32_t p = (uint32_t)((4 * ks + (r & 3)) ^ (4 * (m & 1)));
    uint32_t hi = f2tf32(f);
    float lof = f - __uint_as_float(hi);
    uint32_t lo = f2tf32(lof);
    sts64(base + (uint32_t)m * 256 + p * 16 + (uint32_t)(r >> 2) * 8, hi, lo);
}

__global__ void __launch_bounds__(256, 1)
gemm_tc_kernel(const float* __restrict__ x,
               const float* __restrict__ W_l,
               const float* __restrict__ b_l,
               const float* __restrict__ W_r,
               const float* __restrict__ ln_gamma,
               const float* __restrict__ ln_beta,
               float* __restrict__ out) {
    extern __shared__ char smem[];
    const uint32_t sb = smem_u32(smem);
    const int tid   = threadIdx.x;
    const int lane  = tid & 31;
    const int wid   = tid >> 5;
    const int g     = lane >> 2;     // groupID
    const int tig   = lane & 3;      // threadID in group
    const int warpM = wid & 3;       // 4 warps along M (32 rows each)
    const int warpN = wid >> 2;      // 2 warps along N (64 cols each)
    const int row0  = blockIdx.x * 128;

    if (tid < 128) {
        ((float*)(smem + SM_BL))[tid] = b_l[tid];
        ((float*)(smem + SM_GA))[tid] = ln_gamma[tid];
        ((float*)(smem + SM_BE))[tid] = ln_beta[tid];
    }

    float acc[2][8][4];
    #pragma unroll
    for (int mt = 0; mt < 2; mt++)
        #pragma unroll
        for (int nt = 0; nt < 8; nt++)
            #pragma unroll
            for (int cc = 0; cc < 4; cc++) acc[mt][nt][cc] = 0.f;

    for (int c = 0; c < 8; c++) {
        // ---- stage chunk c (32 k-cols of A and B) ----
        const float* Asrc = (c < 4) ? (g_agg + c * 32) : (x + (c - 4) * 32);
        const float* Bsrc = (c < 4) ? (W_l + c * 32) : (W_r + (c - 4) * 32);
        #pragma unroll
        for (int it = 0; it < 4; it++) {
            int idx = tid + it * 256;
            int m = idx >> 3, q = idx & 7;        // q: float4 index (4 k each)
            int row = row0 + m; if (row >= N_NODES) row = N_NODES - 1;
            float4 av = *(const float4*)(Asrc + (size_t)row * D + q * 4);
            stage_elem(sb + SM_A, m, q * 4 + 0, av.x);
            stage_elem(sb + SM_A, m, q * 4 + 1, av.y);
            stage_elem(sb + SM_A, m, q * 4 + 2, av.z);
            stage_elem(sb + SM_A, m, q * 4 + 3, av.w);
            float4 bv = *(const float4*)(Bsrc + (size_t)m * D + q * 4);
            stage_elem(sb + SM_B, m, q * 4 + 0, bv.x);
            stage_elem(sb + SM_B, m, q * 4 + 1, bv.y);
            stage_elem(sb + SM_B, m, q * 4 + 2, bv.z);
            stage_elem(sb + SM_B, m, q * 4 + 3, bv.w);
        }
        __syncthreads();

        // ---- compute: 4 k-steps of m16n8k8 ----
        #pragma unroll
        for (int ks = 0; ks < 4; ks++) {
            uint32_t ah[2][4], al[2][4];
            #pragma unroll
            for (int mt = 0; mt < 2; mt++) {
                #pragma unroll
                for (int rh = 0; rh < 2; rh++) {
                    int row = warpM * 32 + mt * 16 + g + 8 * rh;
                    uint32_t p = (uint32_t)((4 * ks + tig) ^ (4 * (row & 1)));
                    uint32_t v0, v1, v2, v3;
                    lds128(sb + SM_A + (uint32_t)row * 256 + p * 16, v0, v1, v2, v3);
                    ah[mt][0 + rh] = v0; al[mt][0 + rh] = v1;
                    ah[mt][2 + rh] = v2; al[mt][2 + rh] = v3;
                }
            }
            #pragma unroll
            for (int nt = 0; nt < 8; nt++) {
                int rn = warpN * 64 + nt * 8 + g;
                uint32_t p = (uint32_t)((4 * ks + tig) ^ (4 * (rn & 1)));
                uint32_t bh0, bl0, bh1, bl1;
                lds128(sb + SM_B + (uint32_t)rn * 256 + p * 16, bh0, bl0, bh1, bl1);
                #pragma unroll
                for (int mt = 0; mt < 2; mt++) {
                    MMA3(acc[mt][nt], al[mt][0], al[mt][1], al[mt][2], al[mt][3], bh0, bh1);
                    MMA3(acc[mt][nt], ah[mt][0], ah[mt][1], ah[mt][2], ah[mt][3], bl0, bl1);
                    MMA3(acc[mt][nt], ah[mt][0], ah[mt][1], ah[mt][2], ah[mt][3], bh0, bh1);
                }
            }
        }
        __syncthreads();
    }

    // ---- dump accumulators into C tile (stride 132 floats) ----
    float* C = (float*)(smem + SM_C);
    #pragma unroll
    for (int mt = 0; mt < 2; mt++) {
        #pragma unroll
        for (int nt = 0; nt < 8; nt++) {
            int row = warpM * 32 + mt * 16 + g;
            int col = warpN * 64 + nt * 8 + 2 * tig;
            *(float2*)(C + row * 132 + col)       = make_float2(acc[mt][nt][0], acc[mt][nt][1]);
            *(float2*)(C + (row + 8) * 132 + col) = make_float2(acc[mt][nt][2], acc[mt][nt][3]);
        }
    }
    __syncthreads();

    // ---- bias + GELU + LN stats: thread t handles row (t&127), half (t>>7) ----
    const float* sbl = (const float*)(smem + SM_BL);
    const float* sga = (const float*)(smem + SM_GA);
    const float* sbe = (const float*)(smem + SM_BE);
    float* ps  = (float*)(smem + SM_PS);
    float* pss = (float*)(smem + SM_PSS);

    const int r    = tid & 127;
    const int half = tid >> 7;
    float v[64];
    {
        float s = 0.f, ss = 0.f;
        #pragma unroll
        for (int i = 0; i < 64; i++) {
            int n = half * 64 + i;
            float t = C[r * 132 + n] + sbl[n];
            t = gelu_exact(t);
            v[i] = t;
            s += t;
            ss = fmaf(t, t, ss);
        }
        ps[tid] = s;
        pss[tid] = ss;
    }
    __syncthreads();
    {
        float s  = ps[tid] + ps[tid ^ 128];
        float ss = pss[tid] + pss[tid ^ 128];
        float mu   = s * (1.0f / 128.0f);
        float var  = ss * (1.0f / 128.0f) - mu * mu;
        float rstd = rsqrtf(var + LN_EPS);
        #pragma unroll
        for (int i = 0; i < 64; i++) {
            int n = half * 64 + i;
            C[r * 132 + n] = (v[i] - mu) * rstd * sga[n] + sbe[n];
        }
    }
    __syncthreads();

    // ---- coalesced residual + store ----
    for (int it = 0; it < 16; it++) {
        int idx = tid + it * 256;           // float4 index over 128x128
        int row = idx >> 5, c4 = idx & 31;
        int grow = row0 + row;
        if (grow < N_NODES) {
            float4 cv = *(float4*)(C + row * 132 + c4 * 4);
            float4 xr = *(const float4*)(x + (size_t)grow * D + c4 * 4);
            cv.x += xr.x; cv.y += xr.y; cv.z += xr.z; cv.w += xr.w;
            *(float4*)(out + (size_t)grow * D + c4 * 4) = cv;
        }
    }
}

// ---------------------------------------------------------------------------
extern "C" void kernel_launch(void* const* d_in, const int* in_sizes, int n_in,
                              void* d_out, int out_size) {
    const float* x     = (const float*)d_in[0];
    const int*   ei    = (const int*)d_in[1];
    const float* W_l   = (const float*)d_in[2];
    const float* b_l   = (const float*)d_in[3];
    const float* W_r   = (const float*)d_in[4];
    const float* gamma = (const float*)d_in[5];
    const float* beta  = (const float*)d_in[6];
    float*       out   = (float*)d_out;

    int E = in_sizes[1] / 2;
    if (E > E_MAX) E = E_MAX;

    cudaFuncSetAttribute(gemm_tc_kernel,
                         cudaFuncAttributeMaxDynamicSharedMemorySize, SMEM_G);

    // CSR build
    zero_cnt_kernel<<<(N_NODES + 255) / 256, 256>>>();
    hist_kernel<<<(E + 255) / 256, 256>>>(ei, E);
    int nb = (N_NODES + SCAN_B - 1) / SCAN_B;          // 98 blocks
    scan_partial_kernel<<<nb, SCAN_B>>>(N_NODES);
    scan_sums_kernel<<<1, 128>>>(nb);
    scan_add_kernel<<<(N_NODES + 255) / 256, 256>>>(N_NODES, E);
    csr_fill_kernel<<<(E + 255) / 256, 256>>>(ei, E);

    // Gather-aggregate (no atomics on features)
    long long athreads = (long long)N_NODES * 32;
    aggregate_kernel<<<(int)((athreads + 255) / 256), 256>>>(x);

    // Tensor-core (mma.sync 3xTF32) GEMM + fused epilogue
    int gblocks = (N_NODES + 127) / 128;               // 782
    gemm_tc_kernel<<<gblocks, 256, SMEM_G>>>(x, W_l, b_l, W_r, gamma, beta, out);
}

// round 6
// speedup vs baseline: 2.9742x; 2.2867x over previous
#include <cuda_runtime.h>
#include <math.h>
#include <stdint.h>

#define N_NODES 100000
#define D 128
#define E_MAX 1600000
#define LN_EPS 1e-5f

// Scratch (allocation-free rule: __device__ globals)
__device__ float g_agg[N_NODES * D];     // normalized mean aggregation
__device__ int   g_cnt[N_NODES];
__device__ int   g_off[N_NODES + 1];
__device__ int   g_pos[N_NODES];
__device__ int   g_csr[E_MAX];
__device__ int   g_bsum[128];

__device__ __forceinline__ float gelu_exact(float t) {
    return 0.5f * t * (1.0f + erff(t * 0.70710678118654752440f));
}

__device__ __forceinline__ uint32_t smem_u32(const void* p) {
    uint32_t a;
    asm("{ .reg .u64 t; cvta.to.shared.u64 t, %1; cvt.u32.u64 %0, t; }"
        : "=r"(a) : "l"(p));
    return a;
}
__device__ __forceinline__ uint32_t cvt_bf16x2(float hi_elem, float lo_elem) {
    // returns packed {hi_elem -> high 16, lo_elem -> low 16}
    uint32_t r;
    asm("cvt.rn.bf16x2.f32 %0, %1, %2;" : "=r"(r) : "f"(hi_elem), "f"(lo_elem));
    return r;
}

// ---------------------------------------------------------------------------
// Phase 1: CSR build (histogram -> 2-level exclusive scan -> index scatter)
// ---------------------------------------------------------------------------
__global__ void zero_cnt_kernel() {
    int i = blockIdx.x * blockDim.x + threadIdx.x;
    if (i < N_NODES) g_cnt[i] = 0;
}

__global__ void hist_kernel(const int* __restrict__ ei, int E) {
    int i = blockIdx.x * blockDim.x + threadIdx.x;
    if (i >= E) return;
    int dst = ei[E + i];
    if ((unsigned)dst < N_NODES) atomicAdd(&g_cnt[dst], 1);
}

#define SCAN_B 1024
__global__ void scan_partial_kernel(int n) {
    __shared__ int sdata[SCAN_B];
    int tid = threadIdx.x;
    int i = blockIdx.x * SCAN_B + tid;
    int v = (i < n) ? g_cnt[i] : 0;
    sdata[tid] = v;
    __syncthreads();
    for (int off = 1; off < SCAN_B; off <<= 1) {
        int t = (tid >= off) ? sdata[tid - off] : 0;
        __syncthreads();
        sdata[tid] += t;
        __syncthreads();
    }
    if (i < n) g_off[i] = sdata[tid] - v;   // exclusive within block
    if (tid == SCAN_B - 1) g_bsum[blockIdx.x] = sdata[tid];
}

__global__ void scan_sums_kernel(int nb) {
    __shared__ int sdata[128];
    int tid = threadIdx.x;
    int v = (tid < nb) ? g_bsum[tid] : 0;
    sdata[tid] = v;
    __syncthreads();
    for (int off = 1; off < 128; off <<= 1) {
        int t = (tid >= off) ? sdata[tid - off] : 0;
        __syncthreads();
        sdata[tid] += t;
        __syncthreads();
    }
    if (tid < nb) g_bsum[tid] = sdata[tid] - v;   // exclusive
}

__global__ void scan_add_kernel(int n, int E) {
    int i = blockIdx.x * blockDim.x + threadIdx.x;
    if (i < n) {
        int o = g_off[i] + g_bsum[i / SCAN_B];
        g_off[i] = o;
        g_pos[i] = o;
    }
    if (i == 0) g_off[n] = E;
}

__global__ void csr_fill_kernel(const int* __restrict__ ei, int E) {
    int i = blockIdx.x * blockDim.x + threadIdx.x;
    if (i >= E) return;
    int dst = ei[E + i];
    int src = ei[i];
    if ((unsigned)dst >= N_NODES || (unsigned)src >= N_NODES) return;
    int p = atomicAdd(&g_pos[dst], 1);
    g_csr[p] = src;
}

// ---------------------------------------------------------------------------
// Phase 2: gather-aggregate. One warp per destination node. No atomics.
// 4-wide unroll for MLP (L2 latency ~250cyc wants >=4 rows in flight).
// ---------------------------------------------------------------------------
__global__ void __launch_bounds__(256)
aggregate_kernel(const float* __restrict__ x) {
    int gwarp = (blockIdx.x * blockDim.x + threadIdx.x) >> 5;
    int lane  = threadIdx.x & 31;
    if (gwarp >= N_NODES) return;
    int beg = g_off[gwarp];
    int end = g_off[gwarp + 1];
    float4 acc = make_float4(0.f, 0.f, 0.f, 0.f);
    const float4* x4 = reinterpret_cast<const float4*>(x);

    int e = beg;
    for (; e + 3 < end; e += 4) {
        int s0 = g_csr[e], s1 = g_csr[e + 1], s2 = g_csr[e + 2], s3 = g_csr[e + 3];
        float4 v0 = x4[(size_t)s0 * 32 + lane];
        float4 v1 = x4[(size_t)s1 * 32 + lane];
        float4 v2 = x4[(size_t)s2 * 32 + lane];
        float4 v3 = x4[(size_t)s3 * 32 + lane];
        acc.x += (v0.x + v1.x) + (v2.x + v3.x);
        acc.y += (v0.y + v1.y) + (v2.y + v3.y);
        acc.z += (v0.z + v1.z) + (v2.z + v3.z);
        acc.w += (v0.w + v1.w) + (v2.w + v3.w);
    }
    for (; e < end; e++) {
        float4 v = x4[(size_t)g_csr[e] * 32 + lane];
        acc.x += v.x; acc.y += v.y; acc.z += v.z; acc.w += v.w;
    }
    float rinv = 1.0f / fmaxf((float)(end - beg), 1.0f);
    acc.x *= rinv; acc.y *= rinv; acc.z *= rinv; acc.w *= rinv;
    reinterpret_cast<float4*>(g_agg)[(size_t)gwarp * 32 + lane] = acc;
}

// ---------------------------------------------------------------------------
// Phase 3: split-bf16 mma.sync GEMM + bias + GELU + LayerNorm + residual.
// out = LN(gelu([agg | x] @ [W_l | W_r]^T + b_l)) + x
// a = ah + al (bf16 split); D = ah*bh + ah*bl + al*bh (lo*lo ~ 2^-18, dropped).
// CTA: 256 threads (8 warps, 4x2 warp grid), tile M=128 x N=128, K=256 in
// 8 chunks of 32. Smem slot (16B) = [hiPair0 loPair0 hiPair1 loPair1] so each
// mma fragment (hi+lo halves) is a single lds.128.
// ---------------------------------------------------------------------------
#define SM_A  0          // 128 rows * 128 B = 16384
#define SM_B  16384      // 128 rows * 128 B = 16384
#define SM_C  0          // reuse: 128 * 132 * 4 = 67584
#define SM_BL 67584
#define SM_GA 68096
#define SM_BE 68608
#define SM_PS 69120      // 256 floats partial sums
#define SM_PSS 70144     // 256 floats partial sumsq
#define SMEM_G 71168

#define MMA_BF16(accp, A0,A1,A2,A3, B0,B1) \
    asm volatile("mma.sync.aligned.m16n8k16.row.col.f32.bf16.bf16.f32 " \
        "{%0,%1,%2,%3}, {%4,%5,%6,%7}, {%8,%9}, {%0,%1,%2,%3};" \
        : "+f"((accp)[0]), "+f"((accp)[1]), "+f"((accp)[2]), "+f"((accp)[3]) \
        : "r"(A0), "r"(A1), "r"(A2), "r"(A3), "r"(B0), "r"(B1))

__device__ __forceinline__ void lds128(uint32_t addr, uint32_t& r0, uint32_t& r1,
                                       uint32_t& r2, uint32_t& r3) {
    asm volatile("ld.shared.v4.b32 {%0,%1,%2,%3}, [%4];"
                 : "=r"(r0), "=r"(r1), "=r"(r2), "=r"(r3) : "r"(addr));
}
__device__ __forceinline__ void sts64(uint32_t addr, uint32_t a, uint32_t b) {
    asm volatile("st.shared.v2.b32 [%0], {%1,%2};"
                 :: "r"(addr), "r"(a), "r"(b) : "memory");
}

// Store one k-pair (f0 = k even, f1 = k odd) of row m as (hiPair, loPair).
// Pair index j = k/2 (0..15 within 32-k chunk).
__device__ __forceinline__ void stage_pair(uint32_t base, int m, int j,
                                           float f0, float f1) {
    int ks   = j >> 3;          // k-step within chunk (0..1)
    int jj   = j & 7;
    int half = jj >> 2;         // 0: k in [0,8), 1: k in [8,16) of group
    int tig  = jj & 3;
    uint32_t p = (uint32_t)(((ks << 2) + tig) ^ (m & 7));
    uint32_t addr = base + (uint32_t)m * 128 + p * 16 + (uint32_t)half * 8;
    uint32_t hp = cvt_bf16x2(f1, f0);          // low 16 = f0, high 16 = f1
    float h0 = __uint_as_float(hp << 16);
    float h1 = __uint_as_float(hp & 0xffff0000u);
    uint32_t lp = cvt_bf16x2(f1 - h1, f0 - h0);
    sts64(addr, hp, lp);
}

__global__ void __launch_bounds__(256, 2)
gemm_tc_kernel(const float* __restrict__ x,
               const float* __restrict__ W_l,
               const float* __restrict__ b_l,
               const float* __restrict__ W_r,
               const float* __restrict__ ln_gamma,
               const float* __restrict__ ln_beta,
               float* __restrict__ out) {
    extern __shared__ char smem[];
    const uint32_t sb = smem_u32(smem);
    const int tid   = threadIdx.x;
    const int lane  = tid & 31;
    const int wid   = tid >> 5;
    const int g     = lane >> 2;     // groupID (0..7)
    const int tig   = lane & 3;      // threadID in group
    const int warpM = wid & 3;       // 4 warps along M (32 rows each)
    const int warpN = wid >> 2;      // 2 warps along N (64 cols each)
    const int row0  = blockIdx.x * 128;

    if (tid < 128) {
        ((float*)(smem + SM_BL))[tid] = b_l[tid];
        ((float*)(smem + SM_GA))[tid] = ln_gamma[tid];
        ((float*)(smem + SM_BE))[tid] = ln_beta[tid];
    }

    float acc[2][8][4];
    #pragma unroll
    for (int mt = 0; mt < 2; mt++)
        #pragma unroll
        for (int nt = 0; nt < 8; nt++)
            #pragma unroll
            for (int cc = 0; cc < 4; cc++) acc[mt][nt][cc] = 0.f;

    for (int c = 0; c < 8; c++) {
        // ---- stage chunk c (32 k-cols of A and B) ----
        const float* Asrc = (c < 4) ? (g_agg + c * 32) : (x + (c - 4) * 32);
        const float* Bsrc = (c < 4) ? (W_l + c * 32) : (W_r + (c - 4) * 32);
        #pragma unroll
        for (int it = 0; it < 4; it++) {
            int idx = tid + it * 256;
            int m = idx >> 3, q = idx & 7;        // q: float4 index (4 k each)
            int row = row0 + m; if (row >= N_NODES) row = N_NODES - 1;
            float4 av = *(const float4*)(Asrc + (size_t)row * D + q * 4);
            stage_pair(sb + SM_A, m, 2 * q,     av.x, av.y);
            stage_pair(sb + SM_A, m, 2 * q + 1, av.z, av.w);
            float4 bv = *(const float4*)(Bsrc + (size_t)m * D + q * 4);
            stage_pair(sb + SM_B, m, 2 * q,     bv.x, bv.y);
            stage_pair(sb + SM_B, m, 2 * q + 1, bv.z, bv.w);
        }
        __syncthreads();

        // ---- compute: 2 k-steps of m16n8k16 ----
        #pragma unroll
        for (int ks = 0; ks < 2; ks++) {
            uint32_t ah[2][4], al[2][4];
            #pragma unroll
            for (int mt = 0; mt < 2; mt++) {
                int r0w = warpM * 32 + mt * 16 + g;       // row g
                uint32_t p0 = (uint32_t)(((ks << 2) + tig) ^ (r0w & 7));
                uint32_t v0, v1, v2, v3;
                lds128(sb + SM_A + (uint32_t)r0w * 128 + p0 * 16, v0, v1, v2, v3);
                ah[mt][0] = v0; al[mt][0] = v1; ah[mt][2] = v2; al[mt][2] = v3;
                int r1w = r0w + 8;                        // row g+8
                uint32_t p1 = (uint32_t)(((ks << 2) + tig) ^ (r1w & 7));
                lds128(sb + SM_A + (uint32_t)r1w * 128 + p1 * 16, v0, v1, v2, v3);
                ah[mt][1] = v0; al[mt][1] = v1; ah[mt][3] = v2; al[mt][3] = v3;
            }
            #pragma unroll
            for (int nt = 0; nt < 8; nt++) {
                int rn = warpN * 64 + nt * 8 + g;
                uint32_t p = (uint32_t)(((ks << 2) + tig) ^ (rn & 7));
                uint32_t bh0, bl0, bh1, bl1;
                lds128(sb + SM_B + (uint32_t)rn * 128 + p * 16, bh0, bl0, bh1, bl1);
                #pragma unroll
                for (int mt = 0; mt < 2; mt++) {
                    MMA_BF16(acc[mt][nt], al[mt][0], al[mt][1], al[mt][2], al[mt][3], bh0, bh1);
                    MMA_BF16(acc[mt][nt], ah[mt][0], ah[mt][1], ah[mt][2], ah[mt][3], bl0, bl1);
                    MMA_BF16(acc[mt][nt], ah[mt][0], ah[mt][1], ah[mt][2], ah[mt][3], bh0, bh1);
                }
            }
        }
        __syncthreads();
    }

    // ---- dump accumulators into C tile (stride 132 floats) ----
    float* C = (float*)(smem + SM_C);
    #pragma unroll
    for (int mt = 0; mt < 2; mt++) {
        #pragma unroll
        for (int nt = 0; nt < 8; nt++) {
            int row = warpM * 32 + mt * 16 + g;
            int col = warpN * 64 + nt * 8 + 2 * tig;
            *(float2*)(C + row * 132 + col)       = make_float2(acc[mt][nt][0], acc[mt][nt][1]);
            *(float2*)(C + (row + 8) * 132 + col) = make_float2(acc[mt][nt][2], acc[mt][nt][3]);
        }
    }
    __syncthreads();

    // ---- bias + GELU + LN stats: thread t handles row (t&127), half (t>>7) ----
    const float* sbl = (const float*)(smem + SM_BL);
    const float* sga = (const float*)(smem + SM_GA);
    const float* sbe = (const float*)(smem + SM_BE);
    float* ps  = (float*)(smem + SM_PS);
    float* pss = (float*)(smem + SM_PSS);

    const int r    = tid & 127;
    const int half = tid >> 7;
    float v[64];
    {
        float s = 0.f, ss = 0.f;
        #pragma unroll
        for (int i = 0; i < 64; i++) {
            int n = half * 64 + i;
            float t = C[r * 132 + n] + sbl[n];
            t = gelu_exact(t);
            v[i] = t;
            s += t;
            ss = fmaf(t, t, ss);
        }
        ps[tid] = s;
        pss[tid] = ss;
    }
    __syncthreads();
    {
        float s  = ps[tid] + ps[tid ^ 128];
        float ss = pss[tid] + pss[tid ^ 128];
        float mu   = s * (1.0f / 128.0f);
        float var  = ss * (1.0f / 128.0f) - mu * mu;
        float rstd = rsqrtf(var + LN_EPS);
        #pragma unroll
        for (int i = 0; i < 64; i++) {
            int n = half * 64 + i;
            C[r * 132 + n] = (v[i] - mu) * rstd * sga[n] + sbe[n];
        }
    }
    __syncthreads();

    // ---- coalesced residual + store ----
    for (int it = 0; it < 16; it++) {
        int idx = tid + it * 256;           // float4 index over 128x128
        int row = idx >> 5, c4 = idx & 31;
        int grow = row0 + row;
        if (grow < N_NODES) {
            float4 cv = *(float4*)(C + row * 132 + c4 * 4);
            float4 xr = *(const float4*)(x + (size_t)grow * D + c4 * 4);
            cv.x += xr.x; cv.y += xr.y; cv.z += xr.z; cv.w += xr.w;
            *(float4*)(out + (size_t)grow * D + c4 * 4) = cv;
        }
    }
}

// ---------------------------------------------------------------------------
extern "C" void kernel_launch(void* const* d_in, const int* in_sizes, int n_in,
                              void* d_out, int out_size) {
    const float* x     = (const float*)d_in[0];
    const int*   ei    = (const int*)d_in[1];
    const float* W_l   = (const float*)d_in[2];
    const float* b_l   = (const float*)d_in[3];
    const float* W_r   = (const float*)d_in[4];
    const float* gamma = (const float*)d_in[5];
    const float* beta  = (const float*)d_in[6];
    float*       out   = (float*)d_out;

    int E = in_sizes[1] / 2;
    if (E > E_MAX) E = E_MAX;

    cudaFuncSetAttribute(gemm_tc_kernel,
                         cudaFuncAttributeMaxDynamicSharedMemorySize, SMEM_G);

    // CSR build
    zero_cnt_kernel<<<(N_NODES + 255) / 256, 256>>>();
    hist_kernel<<<(E + 255) / 256, 256>>>(ei, E);
    int nb = (N_NODES + SCAN_B - 1) / SCAN_B;          // 98 blocks
    scan_partial_kernel<<<nb, SCAN_B>>>(N_NODES);
    scan_sums_kernel<<<1, 128>>>(nb);
    scan_add_kernel<<<(N_NODES + 255) / 256, 256>>>(N_NODES, E);
    csr_fill_kernel<<<(E + 255) / 256, 256>>>(ei, E);

    // Gather-aggregate (no atomics on features)
    long long athreads = (long long)N_NODES * 32;
    aggregate_kernel<<<(int)((athreads + 255) / 256), 256>>>(x);

    // Tensor-core (mma.sync split-bf16) GEMM + fused epilogue
    int gblocks = (N_NODES + 127) / 128;               // 782
    gemm_tc_kernel<<<gblocks, 256, SMEM_G>>>(x, W_l, b_l, W_r, gamma, beta, out);
}